// round 1
// baseline (speedup 1.0000x reference)
#include <cuda_runtime.h>
#include <cuda_bf16.h>

// Problem dims (fixed by the reference)
#define S_LEN  1024
#define D_DIM  1024
#define N_ST   64
#define B_SZ   16
#define M_TOT  (B_SZ * S_LEN)      // 16384 rows of (b,s)

// ---------------------------------------------------------------------------
// Scratch (device globals; no runtime allocation allowed)
// ---------------------------------------------------------------------------
__device__ float g_sgA[D_DIM * N_ST];          // sigmoid(A)      [D,N]
__device__ float g_sgB[N_ST * D_DIM];          // sigmoid(W_B)    [N,D]
__device__ float g_sgC[D_DIM * N_ST];          // sigmoid(W_C)    [D,N]
__device__ float g_sgG[D_DIM];                 // sigmoid(gamma)  [D]
__device__ float g_bproj[M_TOT * N_ST];        // x @ sgB.T       [B*S, N]  (4 MB)
__device__ float g_yraw[(size_t)M_TOT * D_DIM];// pre-LN readout  [B*S, D]  (64 MB)

__device__ __forceinline__ float sigf(float v) {
    return 1.0f / (1.0f + expf(-v));
}

// ---------------------------------------------------------------------------
// K1: precompute sigmoids of all weights (tiny)
// ---------------------------------------------------------------------------
__global__ void precompute_kernel(const float* __restrict__ A,
                                  const float* __restrict__ WB,
                                  const float* __restrict__ WC,
                                  const float* __restrict__ gamma) {
    int i = blockIdx.x * blockDim.x + threadIdx.x;
    if (i < D_DIM * N_ST) {
        g_sgA[i] = sigf(A[i]);
        g_sgB[i] = sigf(WB[i]);
        g_sgC[i] = sigf(WC[i]);
    }
    if (i < D_DIM) g_sgG[i] = sigf(gamma[i]);
}

// ---------------------------------------------------------------------------
// K2: Bproj = x @ sgB.T   (M=16384, K=1024, N=64)
// BM=128, BN=64, BK=16, 128 threads, each thread computes 8x8 outputs.
// ---------------------------------------------------------------------------
__global__ __launch_bounds__(128) void bproj_gemm(const float* __restrict__ X) {
    __shared__ float xs[16][128];   // [k][m]
    __shared__ float bs[16][64];    // [k][n]

    const int m0   = blockIdx.x * 128;
    const int tid  = threadIdx.x;
    const int trow = tid >> 3;      // 0..15 -> m offset trow*8
    const int tcol = tid & 7;       // 0..7  -> n offset tcol*8

    float acc[8][8];
    #pragma unroll
    for (int i = 0; i < 8; i++)
        #pragma unroll
        for (int j = 0; j < 8; j++) acc[i][j] = 0.0f;

    for (int k0 = 0; k0 < D_DIM; k0 += 16) {
        // Load x tile: row (m0+tid), 16 floats along k
        const float4* xg = (const float4*)(X + (size_t)(m0 + tid) * D_DIM + k0);
        #pragma unroll
        for (int j = 0; j < 4; j++) {
            float4 v = xg[j];
            xs[j * 4 + 0][tid] = v.x;
            xs[j * 4 + 1][tid] = v.y;
            xs[j * 4 + 2][tid] = v.z;
            xs[j * 4 + 3][tid] = v.w;
        }
        // Load B tile: rows 0..63 of sgB (threads 0..63)
        if (tid < 64) {
            const float4* bg = (const float4*)(g_sgB + (size_t)tid * D_DIM + k0);
            #pragma unroll
            for (int j = 0; j < 4; j++) {
                float4 v = bg[j];
                bs[j * 4 + 0][tid] = v.x;
                bs[j * 4 + 1][tid] = v.y;
                bs[j * 4 + 2][tid] = v.z;
                bs[j * 4 + 3][tid] = v.w;
            }
        }
        __syncthreads();

        #pragma unroll
        for (int kk = 0; kk < 16; kk++) {
            float av[8], bv[8];
            #pragma unroll
            for (int i = 0; i < 8; i++) av[i] = xs[kk][trow * 8 + i];
            #pragma unroll
            for (int j = 0; j < 8; j++) bv[j] = bs[kk][tcol * 8 + j];
            #pragma unroll
            for (int i = 0; i < 8; i++)
                #pragma unroll
                for (int j = 0; j < 8; j++)
                    acc[i][j] = fmaf(av[i], bv[j], acc[i][j]);
        }
        __syncthreads();
    }

    // Write back: 8 rows x 8 cols per thread, 2x float4 per row
    #pragma unroll
    for (int i = 0; i < 8; i++) {
        float* prow = g_bproj + (size_t)(m0 + trow * 8 + i) * N_ST + tcol * 8;
        float4 o0 = make_float4(acc[i][0], acc[i][1], acc[i][2], acc[i][3]);
        float4 o1 = make_float4(acc[i][4], acc[i][5], acc[i][6], acc[i][7]);
        ((float4*)prow)[0] = o0;
        ((float4*)prow)[1] = o1;
    }
}

// ---------------------------------------------------------------------------
// K3: the recurrence. One thread per (b,d); h[64], a[64], c[64] register-
// resident. CTA = 128 threads = 128 consecutive d of one batch; Bproj row
// staged to SMEM with a 1-step double buffer (one __syncthreads per step).
// grid = 128 CTAs (16 batches x 8 d-slices), 1 CTA per SM.
// ---------------------------------------------------------------------------
__global__ __launch_bounds__(128, 1) void recur_kernel(const float* __restrict__ x) {
    const int b = blockIdx.x >> 3;
    const int d = ((blockIdx.x & 7) << 7) | threadIdx.x;

    float a[N_ST], c[N_ST], h[N_ST];
    {
        const float4* arow = (const float4*)(g_sgA + (size_t)d * N_ST);
        const float4* crow = (const float4*)(g_sgC + (size_t)d * N_ST);
        #pragma unroll
        for (int q = 0; q < 16; q++) {
            float4 av = arow[q];
            float4 cv = crow[q];
            a[4 * q + 0] = av.x; a[4 * q + 1] = av.y; a[4 * q + 2] = av.z; a[4 * q + 3] = av.w;
            c[4 * q + 0] = cv.x; c[4 * q + 1] = cv.y; c[4 * q + 2] = cv.z; c[4 * q + 3] = cv.w;
            h[4 * q + 0] = 0.0f; h[4 * q + 1] = 0.0f; h[4 * q + 2] = 0.0f; h[4 * q + 3] = 0.0f;
        }
    }

    __shared__ float4 bb[2][16];
    const float4* bp = (const float4*)(g_bproj + (size_t)b * S_LEN * N_ST);
    const float*  xp = x      + (size_t)b * S_LEN * D_DIM + d;
    float*        yp = g_yraw + (size_t)b * S_LEN * D_DIM + d;

    if (threadIdx.x < 16) bb[0][threadIdx.x] = bp[threadIdx.x];
    float xv = xp[0];
    __syncthreads();

    for (int t = 0; t < S_LEN; t++) {
        const int tn = (t + 1 < S_LEN) ? (t + 1) : t;   // clamped prefetch index
        if (threadIdx.x < 16)
            bb[(t + 1) & 1][threadIdx.x] = bp[(size_t)tn * 16 + threadIdx.x];
        float xnext = xp[(size_t)tn * D_DIM];

        const float4* bcur = bb[t & 1];
        float y0 = 0.0f, y1 = 0.0f, y2 = 0.0f, y3 = 0.0f;
        #pragma unroll
        for (int q = 0; q < 16; q++) {
            float4 bv = bcur[q];
            const int n = 4 * q;
            float h0 = fminf(fmaxf(fmaf(bv.x, xv, h[n + 0] * a[n + 0]), 0.0f), 1.0f);
            float h1 = fminf(fmaxf(fmaf(bv.y, xv, h[n + 1] * a[n + 1]), 0.0f), 1.0f);
            float h2 = fminf(fmaxf(fmaf(bv.z, xv, h[n + 2] * a[n + 2]), 0.0f), 1.0f);
            float h3 = fminf(fmaxf(fmaf(bv.w, xv, h[n + 3] * a[n + 3]), 0.0f), 1.0f);
            h[n + 0] = h0; h[n + 1] = h1; h[n + 2] = h2; h[n + 3] = h3;
            y0 = fmaf(h0, c[n + 0], y0);
            y1 = fmaf(h1, c[n + 1], y1);
            y2 = fmaf(h2, c[n + 2], y2);
            y3 = fmaf(h3, c[n + 3], y3);
        }
        yp[(size_t)t * D_DIM] = (y0 + y1) + (y2 + y3);
        xv = xnext;
        __syncthreads();
    }
}

// ---------------------------------------------------------------------------
// K4: deferred TopologicalNorm + residual + clip.
// One warp per (b,s) row of 1024; two-pass mean/var with the row held in regs
// (avoids E[y^2]-mu^2 cancellation: var ~1e-3 vs mu^2 ~1e3).
// ---------------------------------------------------------------------------
__global__ __launch_bounds__(256) void ln_kernel(const float* __restrict__ x,
                                                 float* __restrict__ out) {
    const int row  = blockIdx.x * 8 + (threadIdx.x >> 5);
    const int lane = threadIdx.x & 31;

    const float4* yr   = (const float4*)(g_yraw + (size_t)row * D_DIM);
    const float4* xr   = (const float4*)(x      + (size_t)row * D_DIM);
    float4*       orow = (float4*)(out + (size_t)row * D_DIM);
    const float4* gr   = (const float4*)g_sgG;

    float4 v[8];
    float sum = 0.0f;
    #pragma unroll
    for (int i = 0; i < 8; i++) {
        v[i] = yr[lane + 32 * i];
        sum += (v[i].x + v[i].y) + (v[i].z + v[i].w);
    }
    #pragma unroll
    for (int o = 16; o > 0; o >>= 1) sum += __shfl_xor_sync(0xffffffffu, sum, o);
    const float mean = sum * (1.0f / 1024.0f);

    float ss = 0.0f;
    #pragma unroll
    for (int i = 0; i < 8; i++) {
        float dx = v[i].x - mean, dy = v[i].y - mean;
        float dz = v[i].z - mean, dw = v[i].w - mean;
        ss += (dx * dx + dy * dy) + (dz * dz + dw * dw);
    }
    #pragma unroll
    for (int o = 16; o > 0; o >>= 1) ss += __shfl_xor_sync(0xffffffffu, ss, o);
    const float rstd = rsqrtf(ss * (1.0f / 1024.0f) + 1e-5f);

    #pragma unroll
    for (int i = 0; i < 8; i++) {
        float4 g4 = gr[lane + 32 * i];
        float4 x4 = xr[lane + 32 * i];
        float4 o4;
        o4.x = fminf(fmaxf((v[i].x - mean) * rstd * g4.x + x4.x, 0.0f), 1.0f);
        o4.y = fminf(fmaxf((v[i].y - mean) * rstd * g4.y + x4.y, 0.0f), 1.0f);
        o4.z = fminf(fmaxf((v[i].z - mean) * rstd * g4.z + x4.z, 0.0f), 1.0f);
        o4.w = fminf(fmaxf((v[i].w - mean) * rstd * g4.w + x4.w, 0.0f), 1.0f);
        orow[lane + 32 * i] = o4;
    }
}

// ---------------------------------------------------------------------------
// Launch
// ---------------------------------------------------------------------------
extern "C" void kernel_launch(void* const* d_in, const int* in_sizes, int n_in,
                              void* d_out, int out_size) {
    const float* x     = (const float*)d_in[0];   // [16,1024,1024]
    const float* A     = (const float*)d_in[1];   // [1024,64]
    const float* WB    = (const float*)d_in[2];   // [64,1024]
    const float* WC    = (const float*)d_in[3];   // [1024,64]
    const float* gamma = (const float*)d_in[4];   // [1024]
    float* out = (float*)d_out;                   // [16,1024,1024]

    precompute_kernel<<<256, 256>>>(A, WB, WC, gamma);
    bproj_gemm<<<M_TOT / 128, 128>>>(x);
    recur_kernel<<<128, 128>>>(x);
    ln_kernel<<<M_TOT / 8, 256>>>(x, out);
}

// round 2
// speedup vs baseline: 1.4970x; 1.4970x over previous
#include <cuda_runtime.h>
#include <cuda_bf16.h>

#define S_LEN  1024
#define D_DIM  1024
#define N_ST   64
#define B_SZ   16
#define M_TOT  (B_SZ * S_LEN)

typedef unsigned long long u64;

// ---------------------------------------------------------------------------
// Scratch (device globals; no runtime allocation allowed)
// ---------------------------------------------------------------------------
__device__ float g_sgA[D_DIM * N_ST];
__device__ float g_sgB[N_ST * D_DIM];
__device__ float g_sgC[D_DIM * N_ST];
__device__ float g_sgG[D_DIM];
__device__ float g_bproj[M_TOT * N_ST];
__device__ float g_yraw[(size_t)M_TOT * D_DIM];

__device__ __forceinline__ float sigf(float v) { return 1.0f / (1.0f + expf(-v)); }

// ---- packed f32x2 helpers (Blackwell sm_103a) ------------------------------
__device__ __forceinline__ u64 pk2(float lo, float hi) {
    u64 r; asm("mov.b64 %0, {%1, %2};" : "=l"(r) : "f"(lo), "f"(hi)); return r;
}
__device__ __forceinline__ void upk2(u64 v, float& lo, float& hi) {
    asm("mov.b64 {%0, %1}, %2;" : "=f"(lo), "=f"(hi) : "l"(v));
}
__device__ __forceinline__ u64 fma2_(u64 a, u64 b, u64 c) {
    u64 d; asm("fma.rn.f32x2 %0, %1, %2, %3;" : "=l"(d) : "l"(a), "l"(b), "l"(c)); return d;
}
__device__ __forceinline__ u64 mul2_(u64 a, u64 b) {
    u64 d; asm("mul.rn.f32x2 %0, %1, %2;" : "=l"(d) : "l"(a), "l"(b)); return d;
}

// ---------------------------------------------------------------------------
// K1: precompute sigmoids
// ---------------------------------------------------------------------------
__global__ void precompute_kernel(const float* __restrict__ A,
                                  const float* __restrict__ WB,
                                  const float* __restrict__ WC,
                                  const float* __restrict__ gamma) {
    int i = blockIdx.x * blockDim.x + threadIdx.x;
    if (i < D_DIM * N_ST) {
        g_sgA[i] = sigf(A[i]);
        g_sgB[i] = sigf(WB[i]);
        g_sgC[i] = sigf(WC[i]);
    }
    if (i < D_DIM) g_sgG[i] = sigf(gamma[i]);
}

// ---------------------------------------------------------------------------
// K2: Bproj = x @ sgB.T   (M=16384, K=1024, N=64), f32x2 inner product.
// BM=128, BN=64, BK=16, 128 threads; each thread: 8 m-rows (4 packed pairs)
// x 8 n-cols.
// ---------------------------------------------------------------------------
__global__ __launch_bounds__(128) void bproj_gemm(const float* __restrict__ X) {
    __shared__ float xs[16][128];   // [k][m]
    __shared__ float bs[16][64];    // [k][n]

    const int m0   = blockIdx.x * 128;
    const int tid  = threadIdx.x;
    const int trow = tid >> 3;      // 0..15 -> m offset trow*8
    const int tcol = tid & 7;       // 0..7  -> n offset tcol*8

    u64 acc[4][8];                  // [m-pair][n]
    #pragma unroll
    for (int i = 0; i < 4; i++)
        #pragma unroll
        for (int j = 0; j < 8; j++) acc[i][j] = 0ull;

    for (int k0 = 0; k0 < D_DIM; k0 += 16) {
        const float4* xg = (const float4*)(X + (size_t)(m0 + tid) * D_DIM + k0);
        #pragma unroll
        for (int j = 0; j < 4; j++) {
            float4 v = xg[j];
            xs[j * 4 + 0][tid] = v.x;
            xs[j * 4 + 1][tid] = v.y;
            xs[j * 4 + 2][tid] = v.z;
            xs[j * 4 + 3][tid] = v.w;
        }
        if (tid < 64) {
            const float4* bg = (const float4*)(g_sgB + (size_t)tid * D_DIM + k0);
            #pragma unroll
            for (int j = 0; j < 4; j++) {
                float4 v = bg[j];
                bs[j * 4 + 0][tid] = v.x;
                bs[j * 4 + 1][tid] = v.y;
                bs[j * 4 + 2][tid] = v.z;
                bs[j * 4 + 3][tid] = v.w;
            }
        }
        __syncthreads();

        #pragma unroll
        for (int kk = 0; kk < 16; kk++) {
            // packed pairs along m (consecutive floats in xs row)
            const u64* xrow = (const u64*)&xs[kk][0];
            u64 av[4];
            #pragma unroll
            for (int i = 0; i < 4; i++) av[i] = xrow[trow * 4 + i];
            #pragma unroll
            for (int j = 0; j < 8; j++) {
                float bf = bs[kk][tcol * 8 + j];
                u64 bd = pk2(bf, bf);
                #pragma unroll
                for (int i = 0; i < 4; i++)
                    acc[i][j] = fma2_(av[i], bd, acc[i][j]);
            }
        }
        __syncthreads();
    }

    // Writeback: each m-pair i covers rows trow*8+2i (lo) and +2i+1 (hi)
    #pragma unroll
    for (int i = 0; i < 4; i++) {
        float lo[8], hi[8];
        #pragma unroll
        for (int j = 0; j < 8; j++) upk2(acc[i][j], lo[j], hi[j]);
        float* p0 = g_bproj + (size_t)(m0 + trow * 8 + 2 * i + 0) * N_ST + tcol * 8;
        float* p1 = g_bproj + (size_t)(m0 + trow * 8 + 2 * i + 1) * N_ST + tcol * 8;
        ((float4*)p0)[0] = make_float4(lo[0], lo[1], lo[2], lo[3]);
        ((float4*)p0)[1] = make_float4(lo[4], lo[5], lo[6], lo[7]);
        ((float4*)p1)[0] = make_float4(hi[0], hi[1], hi[2], hi[3]);
        ((float4*)p1)[1] = make_float4(hi[4], hi[5], hi[6], hi[7]);
    }
}

// ---------------------------------------------------------------------------
// K3: recurrence. One thread per (b,d); h/a/c as 32 packed f32x2 each.
// 4-step groups: x prefetched 4-deep (MLP=4 > DRAM latency), b rows in an
// 8-row smem ring, one __syncthreads per group. fmax(0) dropped (h >= 0 by
// induction: x>=0, sigmoid weights>0, h0=0).
// ---------------------------------------------------------------------------
__global__ __launch_bounds__(128, 1) void recur_kernel(const float* __restrict__ x) {
    const int b   = blockIdx.x >> 3;
    const int d   = ((blockIdx.x & 7) << 7) | threadIdx.x;
    const int tid = threadIdx.x;

    u64 a[32], c[32], h[32];
    {
        const ulonglong2* ar = (const ulonglong2*)(g_sgA + (size_t)d * N_ST);
        const ulonglong2* cr = (const ulonglong2*)(g_sgC + (size_t)d * N_ST);
        #pragma unroll
        for (int q = 0; q < 16; q++) {
            ulonglong2 av = ar[q], cv = cr[q];
            a[2 * q] = av.x; a[2 * q + 1] = av.y;
            c[2 * q] = cv.x; c[2 * q + 1] = cv.y;
            h[2 * q] = 0ull; h[2 * q + 1] = 0ull;
        }
    }

    __shared__ ulonglong2 bb[8][16];   // 8-row ring of Bproj rows (256B each)
    const ulonglong2* bp = (const ulonglong2*)(g_bproj + (size_t)b * S_LEN * N_ST);
    const float* xp = x      + (size_t)b * S_LEN * D_DIM + d;
    float*       yp = g_yraw + (size_t)b * S_LEN * D_DIM + d;

    // preload rows 0..3 (64 threads x one 16B chunk) and x[0..3]
    if (tid < 64) bb[tid >> 4][tid & 15] = bp[tid];
    float xc[4];
    #pragma unroll
    for (int i = 0; i < 4; i++) xc[i] = xp[(size_t)i * D_DIM];
    __syncthreads();

    for (int g = 0; g < S_LEN / 4; g++) {
        const int t0i = g * 4;
        float xn[4] = {0.f, 0.f, 0.f, 0.f};
        if (g < S_LEN / 4 - 1) {
            if (tid < 64) {
                const int r = t0i + 4 + (tid >> 4);
                bb[r & 7][tid & 15] = bp[(size_t)r * 16 + (tid & 15)];
            }
            #pragma unroll
            for (int i = 0; i < 4; i++) xn[i] = xp[(size_t)(t0i + 4 + i) * D_DIM];
        }

        #pragma unroll
        for (int tt = 0; tt < 4; tt++) {
            const ulonglong2* bcur = bb[(t0i + tt) & 7];
            const u64 xx = pk2(xc[tt], xc[tt]);
            u64 y0 = 0ull, y1 = 0ull;
            #pragma unroll
            for (int q = 0; q < 16; q++) {
                ulonglong2 bv = bcur[q];
                u64 p0 = fma2_(bv.x, xx, mul2_(h[2 * q],     a[2 * q]));
                u64 p1 = fma2_(bv.y, xx, mul2_(h[2 * q + 1], a[2 * q + 1]));
                float e0, e1, f0, f1;
                upk2(p0, e0, e1);
                upk2(p1, f0, f1);
                e0 = fminf(e0, 1.0f); e1 = fminf(e1, 1.0f);
                f0 = fminf(f0, 1.0f); f1 = fminf(f1, 1.0f);
                p0 = pk2(e0, e1);
                p1 = pk2(f0, f1);
                h[2 * q]     = p0;
                h[2 * q + 1] = p1;
                y0 = fma2_(p0, c[2 * q],     y0);
                y1 = fma2_(p1, c[2 * q + 1], y1);
            }
            float s0, s1, s2, s3;
            upk2(y0, s0, s1);
            upk2(y1, s2, s3);
            yp[(size_t)(t0i + tt) * D_DIM] = (s0 + s1) + (s2 + s3);
        }

        #pragma unroll
        for (int i = 0; i < 4; i++) xc[i] = xn[i];
        __syncthreads();
    }
}

// ---------------------------------------------------------------------------
// K4: deferred TopologicalNorm + residual + clip (two-pass, row in regs)
// ---------------------------------------------------------------------------
__global__ __launch_bounds__(256) void ln_kernel(const float* __restrict__ x,
                                                 float* __restrict__ out) {
    const int row  = blockIdx.x * 8 + (threadIdx.x >> 5);
    const int lane = threadIdx.x & 31;

    const float4* yr   = (const float4*)(g_yraw + (size_t)row * D_DIM);
    const float4* xr   = (const float4*)(x      + (size_t)row * D_DIM);
    float4*       orow = (float4*)(out + (size_t)row * D_DIM);
    const float4* gr   = (const float4*)g_sgG;

    float4 v[8];
    float sum = 0.0f;
    #pragma unroll
    for (int i = 0; i < 8; i++) {
        v[i] = yr[lane + 32 * i];
        sum += (v[i].x + v[i].y) + (v[i].z + v[i].w);
    }
    #pragma unroll
    for (int o = 16; o > 0; o >>= 1) sum += __shfl_xor_sync(0xffffffffu, sum, o);
    const float mean = sum * (1.0f / 1024.0f);

    float ss = 0.0f;
    #pragma unroll
    for (int i = 0; i < 8; i++) {
        float dx = v[i].x - mean, dy = v[i].y - mean;
        float dz = v[i].z - mean, dw = v[i].w - mean;
        ss += (dx * dx + dy * dy) + (dz * dz + dw * dw);
    }
    #pragma unroll
    for (int o = 16; o > 0; o >>= 1) ss += __shfl_xor_sync(0xffffffffu, ss, o);
    const float rstd = rsqrtf(ss * (1.0f / 1024.0f) + 1e-5f);

    #pragma unroll
    for (int i = 0; i < 8; i++) {
        float4 g4 = gr[lane + 32 * i];
        float4 x4 = xr[lane + 32 * i];
        float4 o4;
        o4.x = fminf(fmaxf((v[i].x - mean) * rstd * g4.x + x4.x, 0.0f), 1.0f);
        o4.y = fminf(fmaxf((v[i].y - mean) * rstd * g4.y + x4.y, 0.0f), 1.0f);
        o4.z = fminf(fmaxf((v[i].z - mean) * rstd * g4.z + x4.z, 0.0f), 1.0f);
        o4.w = fminf(fmaxf((v[i].w - mean) * rstd * g4.w + x4.w, 0.0f), 1.0f);
        orow[lane + 32 * i] = o4;
    }
}

// ---------------------------------------------------------------------------
extern "C" void kernel_launch(void* const* d_in, const int* in_sizes, int n_in,
                              void* d_out, int out_size) {
    const float* x     = (const float*)d_in[0];
    const float* A     = (const float*)d_in[1];
    const float* WB    = (const float*)d_in[2];
    const float* WC    = (const float*)d_in[3];
    const float* gamma = (const float*)d_in[4];
    float* out = (float*)d_out;

    precompute_kernel<<<256, 256>>>(A, WB, WC, gamma);
    bproj_gemm<<<M_TOT / 128, 128>>>(x);
    recur_kernel<<<128, 128>>>(x);
    ln_kernel<<<M_TOT / 8, 256>>>(x, out);
}

// round 6
// speedup vs baseline: 1.5126x; 1.0104x over previous
#include <cuda_runtime.h>
#include <cuda_bf16.h>

#define S_LEN  1024
#define D_DIM  1024
#define N_ST   64
#define B_SZ   16
#define M_TOT  (B_SZ * S_LEN)

typedef unsigned long long u64;

// ---------------------------------------------------------------------------
// Scratch (device globals; no runtime allocation allowed)
// ---------------------------------------------------------------------------
__device__ float g_sgA[D_DIM * N_ST];
__device__ float g_sgB[N_ST * D_DIM];
__device__ float g_sgC[D_DIM * N_ST];
__device__ float g_sgG[D_DIM];
__device__ float g_bproj[M_TOT * N_ST];
__device__ float g_yraw[(size_t)M_TOT * D_DIM];

__device__ __forceinline__ float sigf(float v) { return 1.0f / (1.0f + expf(-v)); }

// ---- packed f32x2 helpers (Blackwell sm_103a) ------------------------------
__device__ __forceinline__ u64 pk2(float lo, float hi) {
    u64 r; asm("mov.b64 %0, {%1, %2};" : "=l"(r) : "f"(lo), "f"(hi)); return r;
}
__device__ __forceinline__ void upk2(u64 v, float& lo, float& hi) {
    asm("mov.b64 {%0, %1}, %2;" : "=f"(lo), "=f"(hi) : "l"(v));
}
__device__ __forceinline__ u64 fma2_(u64 a, u64 b, u64 c) {
    u64 d; asm("fma.rn.f32x2 %0, %1, %2, %3;" : "=l"(d) : "l"(a), "l"(b), "l"(c)); return d;
}
__device__ __forceinline__ u64 mul2_(u64 a, u64 b) {
    u64 d; asm("mul.rn.f32x2 %0, %1, %2;" : "=l"(d) : "l"(a), "l"(b)); return d;
}
__device__ __forceinline__ u64 min1_2(u64 v) {   // min(v, 1.0) per lane
    float lo, hi;
    upk2(v, lo, hi);
    lo = fminf(lo, 1.0f);
    hi = fminf(hi, 1.0f);
    return pk2(lo, hi);
}

// ---------------------------------------------------------------------------
// K1: precompute sigmoids
// ---------------------------------------------------------------------------
__global__ void precompute_kernel(const float* __restrict__ A,
                                  const float* __restrict__ WB,
                                  const float* __restrict__ WC,
                                  const float* __restrict__ gamma) {
    int i = blockIdx.x * blockDim.x + threadIdx.x;
    if (i < D_DIM * N_ST) {
        g_sgA[i] = sigf(A[i]);
        g_sgB[i] = sigf(WB[i]);
        g_sgC[i] = sigf(WC[i]);
    }
    if (i < D_DIM) g_sgG[i] = sigf(gamma[i]);
}

// ---------------------------------------------------------------------------
// K2: Bproj = x @ sgB.T   (M=16384, K=1024, N=64), f32x2 inner product.
// ---------------------------------------------------------------------------
__global__ __launch_bounds__(128) void bproj_gemm(const float* __restrict__ X) {
    __shared__ float xs[16][128];   // [k][m]
    __shared__ float bs[16][64];    // [k][n]

    const int m0   = blockIdx.x * 128;
    const int tid  = threadIdx.x;
    const int trow = tid >> 3;
    const int tcol = tid & 7;

    u64 acc[4][8];
    #pragma unroll
    for (int i = 0; i < 4; i++)
        #pragma unroll
        for (int j = 0; j < 8; j++) acc[i][j] = 0ull;

    for (int k0 = 0; k0 < D_DIM; k0 += 16) {
        const float4* xg = (const float4*)(X + (size_t)(m0 + tid) * D_DIM + k0);
        #pragma unroll
        for (int j = 0; j < 4; j++) {
            float4 v = xg[j];
            xs[j * 4 + 0][tid] = v.x;
            xs[j * 4 + 1][tid] = v.y;
            xs[j * 4 + 2][tid] = v.z;
            xs[j * 4 + 3][tid] = v.w;
        }
        if (tid < 64) {
            const float4* bg = (const float4*)(g_sgB + (size_t)tid * D_DIM + k0);
            #pragma unroll
            for (int j = 0; j < 4; j++) {
                float4 v = bg[j];
                bs[j * 4 + 0][tid] = v.x;
                bs[j * 4 + 1][tid] = v.y;
                bs[j * 4 + 2][tid] = v.z;
                bs[j * 4 + 3][tid] = v.w;
            }
        }
        __syncthreads();

        #pragma unroll
        for (int kk = 0; kk < 16; kk++) {
            const u64* xrow = (const u64*)&xs[kk][0];
            u64 av[4];
            #pragma unroll
            for (int i = 0; i < 4; i++) av[i] = xrow[trow * 4 + i];
            #pragma unroll
            for (int j = 0; j < 8; j++) {
                float bf = bs[kk][tcol * 8 + j];
                u64 bd = pk2(bf, bf);
                #pragma unroll
                for (int i = 0; i < 4; i++)
                    acc[i][j] = fma2_(av[i], bd, acc[i][j]);
            }
        }
        __syncthreads();
    }

    #pragma unroll
    for (int i = 0; i < 4; i++) {
        float lo[8], hi[8];
        #pragma unroll
        for (int j = 0; j < 8; j++) upk2(acc[i][j], lo[j], hi[j]);
        float* p0 = g_bproj + (size_t)(m0 + trow * 8 + 2 * i + 0) * N_ST + tcol * 8;
        float* p1 = g_bproj + (size_t)(m0 + trow * 8 + 2 * i + 1) * N_ST + tcol * 8;
        ((float4*)p0)[0] = make_float4(lo[0], lo[1], lo[2], lo[3]);
        ((float4*)p0)[1] = make_float4(lo[4], lo[5], lo[6], lo[7]);
        ((float4*)p1)[0] = make_float4(hi[0], hi[1], hi[2], hi[3]);
        ((float4*)p1)[1] = make_float4(hi[4], hi[5], hi[6], hi[7]);
    }
}

// ---------------------------------------------------------------------------
// K3: recurrence, split-N. Lane pair (2j, 2j+1) handles one (b,d):
// lane 2j -> states [0,32), lane 2j+1 -> states [32,64).
// CTA = 256 threads = 128 d of one batch slice; 128 CTAs -> 1 CTA/SM,
// 2 warps/SMSP (dual-issue + latency hiding vs R2's single warp).
// b rows in an 8-row smem ring with interleaved chunk layout
// [c0_lo, c0_hi, c1_lo, c1_hi, ...] so even/odd lanes hit adjacent 16B
// (no 2-way bank conflict). One __syncthreads per 4 steps; x prefetch 4-deep.
// fmax(0) dropped: h >= 0 by induction (x>=0, sigmoid weights>0, h0=0).
// ---------------------------------------------------------------------------
__global__ __launch_bounds__(256, 1) void recur_kernel(const float* __restrict__ x) {
    const int b    = blockIdx.x >> 3;
    const int tid  = threadIdx.x;
    const int dl   = tid >> 1;        // 0..127
    const int half = tid & 1;         // which 32-state half
    const int d    = ((blockIdx.x & 7) << 7) | dl;

    u64 a[16], c[16], h[16];          // 32 states as 16 packed pairs
    {
        const ulonglong2* ar = (const ulonglong2*)(g_sgA + (size_t)d * N_ST + half * 32);
        const ulonglong2* cr = (const ulonglong2*)(g_sgC + (size_t)d * N_ST + half * 32);
        #pragma unroll
        for (int q = 0; q < 8; q++) {
            ulonglong2 av = ar[q], cv = cr[q];
            a[2 * q] = av.x; a[2 * q + 1] = av.y;
            c[2 * q] = cv.x; c[2 * q + 1] = cv.y;
            h[2 * q] = 0ull; h[2 * q + 1] = 0ull;
        }
    }

    // ring: bb[row][2*q + half] holds b chunk (half*8 + q) of that row
    __shared__ ulonglong2 bb[8][16];
    const ulonglong2* bp = (const ulonglong2*)(g_bproj + (size_t)b * S_LEN * N_ST);
    const float* xp = x      + (size_t)b * S_LEN * D_DIM + d;
    float*       yp = g_yraw + (size_t)b * S_LEN * D_DIM + d;

    // preload rows 0..3 and x[0..3]
    if (tid < 64) {
        const int r = tid >> 4, cch = tid & 15;
        bb[r][((cch & 7) << 1) | (cch >> 3)] = bp[(size_t)r * 16 + cch];
    }
    float xc[4];
    #pragma unroll
    for (int i = 0; i < 4; i++) xc[i] = xp[(size_t)i * D_DIM];
    __syncthreads();

    for (int g = 0; g < S_LEN / 4; g++) {
        const int t0i = g * 4;
        float xn[4] = {0.f, 0.f, 0.f, 0.f};
        if (g < S_LEN / 4 - 1) {
            if (tid < 64) {
                const int r = t0i + 4 + (tid >> 4), cch = tid & 15;
                bb[r & 7][((cch & 7) << 1) | (cch >> 3)] = bp[(size_t)r * 16 + cch];
            }
            #pragma unroll
            for (int i = 0; i < 4; i++) xn[i] = xp[(size_t)(t0i + 4 + i) * D_DIM];
        }

        #pragma unroll
        for (int tt = 0; tt < 4; tt++) {
            const ulonglong2* bcur = bb[(t0i + tt) & 7];
            const u64 xx = pk2(xc[tt], xc[tt]);
            u64 y0 = 0ull, y1 = 0ull;
            #pragma unroll
            for (int q = 0; q < 8; q++) {
                ulonglong2 bv = bcur[2 * q + half];
                u64 p0 = min1_2(fma2_(bv.x, xx, mul2_(h[2 * q],     a[2 * q])));
                u64 p1 = min1_2(fma2_(bv.y, xx, mul2_(h[2 * q + 1], a[2 * q + 1])));
                h[2 * q]     = p0;
                h[2 * q + 1] = p1;
                y0 = fma2_(p0, c[2 * q],     y0);
                y1 = fma2_(p1, c[2 * q + 1], y1);
            }
            float s0, s1, s2, s3;
            upk2(y0, s0, s1);
            upk2(y1, s2, s3);
            float part = (s0 + s1) + (s2 + s3);
            float tot  = part + __shfl_xor_sync(0xffffffffu, part, 1);
            if (half == 0) yp[(size_t)(t0i + tt) * D_DIM] = tot;
        }

        #pragma unroll
        for (int i = 0; i < 4; i++) xc[i] = xn[i];
        __syncthreads();
    }
}

// ---------------------------------------------------------------------------
// K4: deferred TopologicalNorm + residual + clip (two-pass, row in regs)
// ---------------------------------------------------------------------------
__global__ __launch_bounds__(256) void ln_kernel(const float* __restrict__ x,
                                                 float* __restrict__ out) {
    const int row  = blockIdx.x * 8 + (threadIdx.x >> 5);
    const int lane = threadIdx.x & 31;

    const float4* yr   = (const float4*)(g_yraw + (size_t)row * D_DIM);
    const float4* xr   = (const float4*)(x      + (size_t)row * D_DIM);
    float4*       orow = (float4*)(out + (size_t)row * D_DIM);
    const float4* gr   = (const float4*)g_sgG;

    float4 v[8];
    float sum = 0.0f;
    #pragma unroll
    for (int i = 0; i < 8; i++) {
        v[i] = yr[lane + 32 * i];
        sum += (v[i].x + v[i].y) + (v[i].z + v[i].w);
    }
    #pragma unroll
    for (int o = 16; o > 0; o >>= 1) sum += __shfl_xor_sync(0xffffffffu, sum, o);
    const float mean = sum * (1.0f / 1024.0f);

    float ss = 0.0f;
    #pragma unroll
    for (int i = 0; i < 8; i++) {
        float dx = v[i].x - mean, dy = v[i].y - mean;
        float dz = v[i].z - mean, dw = v[i].w - mean;
        ss += (dx * dx + dy * dy) + (dz * dz + dw * dw);
    }
    #pragma unroll
    for (int o = 16; o > 0; o >>= 1) ss += __shfl_xor_sync(0xffffffffu, ss, o);
    const float rstd = rsqrtf(ss * (1.0f / 1024.0f) + 1e-5f);

    #pragma unroll
    for (int i = 0; i < 8; i++) {
        float4 g4 = gr[lane + 32 * i];
        float4 x4 = xr[lane + 32 * i];
        float4 o4;
        o4.x = fminf(fmaxf((v[i].x - mean) * rstd * g4.x + x4.x, 0.0f), 1.0f);
        o4.y = fminf(fmaxf((v[i].y - mean) * rstd * g4.y + x4.y, 0.0f), 1.0f);
        o4.z = fminf(fmaxf((v[i].z - mean) * rstd * g4.z + x4.z, 0.0f), 1.0f);
        o4.w = fminf(fmaxf((v[i].w - mean) * rstd * g4.w + x4.w, 0.0f), 1.0f);
        orow[lane + 32 * i] = o4;
    }
}

// ---------------------------------------------------------------------------
extern "C" void kernel_launch(void* const* d_in, const int* in_sizes, int n_in,
                              void* d_out, int out_size) {
    const float* x     = (const float*)d_in[0];
    const float* A     = (const float*)d_in[1];
    const float* WB    = (const float*)d_in[2];
    const float* WC    = (const float*)d_in[3];
    const float* gamma = (const float*)d_in[4];
    float* out = (float*)d_out;

    precompute_kernel<<<256, 256>>>(A, WB, WC, gamma);
    bproj_gemm<<<M_TOT / 128, 128>>>(x);
    recur_kernel<<<128, 256>>>(x);
    ln_kernel<<<M_TOT / 8, 256>>>(x, out);
}

// round 8
// speedup vs baseline: 1.9890x; 1.3149x over previous
#include <cuda_runtime.h>
#include <cuda_bf16.h>

#define S_LEN  1024
#define D_DIM  1024
#define N_ST   64
#define B_SZ   16
#define M_TOT  (B_SZ * S_LEN)

typedef unsigned long long u64;

// ---------------------------------------------------------------------------
// Scratch (device globals; no runtime allocation allowed)
// ---------------------------------------------------------------------------
__device__ float g_sgA[D_DIM * N_ST];
__device__ float g_sgB[N_ST * D_DIM];
__device__ float g_sgC[D_DIM * N_ST];
__device__ float g_sgG[D_DIM];
__device__ float g_bproj[M_TOT * N_ST];
__device__ float g_minb[M_TOT];                 // min_n bproj[row, n]
__device__ float g_sumCh[D_DIM * 2];            // per (d, half) sum of sgC
__device__ float g_yraw[(size_t)M_TOT * D_DIM];

__device__ __forceinline__ float sigf(float v) { return 1.0f / (1.0f + expf(-v)); }

// ---- packed f32x2 helpers (Blackwell sm_103a) ------------------------------
__device__ __forceinline__ u64 pk2(float lo, float hi) {
    u64 r; asm("mov.b64 %0, {%1, %2};" : "=l"(r) : "f"(lo), "f"(hi)); return r;
}
__device__ __forceinline__ void upk2(u64 v, float& lo, float& hi) {
    asm("mov.b64 {%0, %1}, %2;" : "=f"(lo), "=f"(hi) : "l"(v));
}
__device__ __forceinline__ u64 fma2_(u64 a, u64 b, u64 c) {
    u64 d; asm("fma.rn.f32x2 %0, %1, %2, %3;" : "=l"(d) : "l"(a), "l"(b), "l"(c)); return d;
}
__device__ __forceinline__ u64 mul2_(u64 a, u64 b) {
    u64 d; asm("mul.rn.f32x2 %0, %1, %2;" : "=l"(d) : "l"(a), "l"(b)); return d;
}
__device__ __forceinline__ u64 min1_2(u64 v) {   // min(v, 1.0) per lane
    float lo, hi;
    upk2(v, lo, hi);
    lo = fminf(lo, 1.0f);
    hi = fminf(hi, 1.0f);
    return pk2(lo, hi);
}

// ---------------------------------------------------------------------------
// K1: precompute sigmoids
// ---------------------------------------------------------------------------
__global__ void precompute_kernel(const float* __restrict__ A,
                                  const float* __restrict__ WB,
                                  const float* __restrict__ WC,
                                  const float* __restrict__ gamma) {
    int i = blockIdx.x * blockDim.x + threadIdx.x;
    if (i < D_DIM * N_ST) {
        g_sgA[i] = sigf(A[i]);
        g_sgB[i] = sigf(WB[i]);
        g_sgC[i] = sigf(WC[i]);
    }
    if (i < D_DIM) g_sgG[i] = sigf(gamma[i]);
}

// ---------------------------------------------------------------------------
// K2: Bproj = x @ sgB.T  (M=16384, K=1024, N=64), f32x2, 256 thr (2 w/SMSP).
// BM=128, BN=64, BK=16; each thread computes 4 m-rows x 8 n-cols.
// ---------------------------------------------------------------------------
__global__ __launch_bounds__(256) void bproj_gemm(const float* __restrict__ X) {
    __shared__ __align__(16) float xs[16][128];   // [k][m]
    __shared__ __align__(16) float bs[16][64];    // [k][n]

    const int m0   = blockIdx.x * 128;
    const int tid  = threadIdx.x;
    const int trow = tid >> 3;      // 0..31 -> rows trow*4 .. trow*4+3
    const int tcol = tid & 7;       // 0..7  -> cols tcol*8 .. tcol*8+7

    u64 acc[2][8];
    #pragma unroll
    for (int i = 0; i < 2; i++)
        #pragma unroll
        for (int j = 0; j < 8; j++) acc[i][j] = 0ull;

    const int xm  = tid & 127, xkq = tid >> 7;   // x tile: 2 float4 per thread
    const int bn  = tid & 63,  bkq = tid >> 6;   // b tile: 1 float4 per thread

    for (int k0 = 0; k0 < D_DIM; k0 += 16) {
        const float4* xg = (const float4*)(X + (size_t)(m0 + xm) * D_DIM + k0 + xkq * 8);
        #pragma unroll
        for (int j = 0; j < 2; j++) {
            float4 v = xg[j];
            const int k = xkq * 8 + j * 4;
            xs[k + 0][xm] = v.x; xs[k + 1][xm] = v.y;
            xs[k + 2][xm] = v.z; xs[k + 3][xm] = v.w;
        }
        {
            float4 v = *(const float4*)(g_sgB + (size_t)bn * D_DIM + k0 + bkq * 4);
            const int k = bkq * 4;
            bs[k + 0][bn] = v.x; bs[k + 1][bn] = v.y;
            bs[k + 2][bn] = v.z; bs[k + 3][bn] = v.w;
        }
        __syncthreads();

        #pragma unroll
        for (int kk = 0; kk < 16; kk++) {
            const u64* xrow = (const u64*)&xs[kk][0];
            u64 av0 = xrow[trow * 2 + 0];
            u64 av1 = xrow[trow * 2 + 1];
            #pragma unroll
            for (int j = 0; j < 8; j++) {
                float bf = bs[kk][tcol * 8 + j];
                u64 bd = pk2(bf, bf);
                acc[0][j] = fma2_(av0, bd, acc[0][j]);
                acc[1][j] = fma2_(av1, bd, acc[1][j]);
            }
        }
        __syncthreads();
    }

    #pragma unroll
    for (int i = 0; i < 2; i++) {
        float lo[8], hi[8];
        #pragma unroll
        for (int j = 0; j < 8; j++) upk2(acc[i][j], lo[j], hi[j]);
        float* p0 = g_bproj + (size_t)(m0 + trow * 4 + 2 * i + 0) * N_ST + tcol * 8;
        float* p1 = g_bproj + (size_t)(m0 + trow * 4 + 2 * i + 1) * N_ST + tcol * 8;
        ((float4*)p0)[0] = make_float4(lo[0], lo[1], lo[2], lo[3]);
        ((float4*)p0)[1] = make_float4(lo[4], lo[5], lo[6], lo[7]);
        ((float4*)p1)[0] = make_float4(hi[0], hi[1], hi[2], hi[3]);
        ((float4*)p1)[1] = make_float4(hi[4], hi[5], hi[6], hi[7]);
    }
}

// ---------------------------------------------------------------------------
// K2b: aux — row-min of Bproj (g_minb) and per-(d,half) sums of sgC (g_sumCh)
// ---------------------------------------------------------------------------
__global__ void aux_kernel() {
    int i = blockIdx.x * blockDim.x + threadIdx.x;
    if (i < M_TOT) {
        const float4* r = (const float4*)(g_bproj + (size_t)i * N_ST);
        float m = 1e30f;
        #pragma unroll
        for (int q = 0; q < 16; q++) {
            float4 v = r[q];
            m = fminf(m, fminf(fminf(v.x, v.y), fminf(v.z, v.w)));
        }
        g_minb[i] = m;
    } else if (i < M_TOT + 2 * D_DIM) {
        int j = i - M_TOT;
        int d = j >> 1, half = j & 1;
        const float* c = g_sgC + (size_t)d * N_ST + half * 32;
        float s = 0.0f;
        for (int q = 0; q < 32; q++) s += c[q];
        g_sumCh[j] = s;
    }
}

__global__ void noop_kernel() {}

// ---------------------------------------------------------------------------
// K3: recurrence with exact saturation fast path.
// Lane pair (2j,2j+1) handles (b,d); lane half h-states [half*32, half*32+32).
// Fast path (x*minb >= 1): h saturates to exactly 1 for ALL n, so y = sumCh
// and we only set the 'hone' flag — no LDS, no FMA loop. Slow path resolves
// hone with SELs (h_eff = hone ? 1 : h), then clears it.
// ---------------------------------------------------------------------------
__global__ __launch_bounds__(256, 1) void recur_kernel(const float* __restrict__ x) {
    const int b    = blockIdx.x >> 3;
    const int tid  = threadIdx.x;
    const int dl   = tid >> 1;
    const int half = tid & 1;
    const int d    = ((blockIdx.x & 7) << 7) | dl;

    u64 a[16], c[16], h[16];
    {
        const ulonglong2* ar = (const ulonglong2*)(g_sgA + (size_t)d * N_ST + half * 32);
        const ulonglong2* cr = (const ulonglong2*)(g_sgC + (size_t)d * N_ST + half * 32);
        #pragma unroll
        for (int q = 0; q < 8; q++) {
            ulonglong2 av = ar[q], cv = cr[q];
            a[2 * q] = av.x; a[2 * q + 1] = av.y;
            c[2 * q] = cv.x; c[2 * q + 1] = cv.y;
            h[2 * q] = 0ull; h[2 * q + 1] = 0ull;
        }
    }
    const float sumCh = g_sumCh[((blockIdx.x & 7) << 8) | tid];   // = d*2+half
    const u64 one2 = pk2(1.0f, 1.0f);
    bool hone = false;

    __shared__ ulonglong2 bb[8][16];
    const ulonglong2* bp = (const ulonglong2*)(g_bproj + (size_t)b * S_LEN * N_ST);
    const float* xp = x      + (size_t)b * S_LEN * D_DIM + d;
    const float* mp = g_minb + (size_t)b * S_LEN;
    float*       yp = g_yraw + (size_t)b * S_LEN * D_DIM + d;

    if (tid < 64) {
        const int r = tid >> 4, cch = tid & 15;
        bb[r][((cch & 7) << 1) | (cch >> 3)] = bp[(size_t)r * 16 + cch];
    }
    float xc[4], mc[4];
    #pragma unroll
    for (int i = 0; i < 4; i++) {
        xc[i] = xp[(size_t)i * D_DIM];
        mc[i] = mp[i];
    }
    __syncthreads();

    for (int g = 0; g < S_LEN / 4; g++) {
        const int t0i = g * 4;
        float xn[4] = {0.f, 0.f, 0.f, 0.f};
        float mn[4] = {0.f, 0.f, 0.f, 0.f};
        if (g < S_LEN / 4 - 1) {
            if (tid < 64) {
                const int r = t0i + 4 + (tid >> 4), cch = tid & 15;
                bb[r & 7][((cch & 7) << 1) | (cch >> 3)] = bp[(size_t)r * 16 + cch];
            }
            #pragma unroll
            for (int i = 0; i < 4; i++) {
                xn[i] = xp[(size_t)(t0i + 4 + i) * D_DIM];
                mn[i] = mp[t0i + 4 + i];
            }
        }

        #pragma unroll
        for (int tt = 0; tt < 4; tt++) {
            const float xv = xc[tt];
            float part;
            if (xv * mc[tt] >= 1.0f) {
                // exact saturation: h[n] = 1 for all n
                part = sumCh;
                hone = true;
            } else {
                const ulonglong2* bcur = bb[(t0i + tt) & 7];
                const u64 xx = pk2(xv, xv);
                u64 y0 = 0ull, y1 = 0ull;
                #pragma unroll
                for (int q = 0; q < 8; q++) {
                    ulonglong2 bv = bcur[2 * q + half];
                    u64 h0 = hone ? one2 : h[2 * q];
                    u64 h1 = hone ? one2 : h[2 * q + 1];
                    u64 p0 = min1_2(fma2_(bv.x, xx, mul2_(h0, a[2 * q])));
                    u64 p1 = min1_2(fma2_(bv.y, xx, mul2_(h1, a[2 * q + 1])));
                    h[2 * q]     = p0;
                    h[2 * q + 1] = p1;
                    y0 = fma2_(p0, c[2 * q],     y0);
                    y1 = fma2_(p1, c[2 * q + 1], y1);
                }
                hone = false;
                float s0, s1, s2, s3;
                upk2(y0, s0, s1);
                upk2(y1, s2, s3);
                part = (s0 + s1) + (s2 + s3);
            }
            float tot = part + __shfl_xor_sync(0xffffffffu, part, 1);
            if (half == 0) yp[(size_t)(t0i + tt) * D_DIM] = tot;
        }

        #pragma unroll
        for (int i = 0; i < 4; i++) { xc[i] = xn[i]; mc[i] = mn[i]; }
        __syncthreads();
    }
}

// ---------------------------------------------------------------------------
// K4: deferred TopologicalNorm + residual + clip (two-pass, row in regs)
// ---------------------------------------------------------------------------
__global__ __launch_bounds__(256) void ln_kernel(const float* __restrict__ x,
                                                 float* __restrict__ out) {
    const int row  = blockIdx.x * 8 + (threadIdx.x >> 5);
    const int lane = threadIdx.x & 31;

    const float4* yr   = (const float4*)(g_yraw + (size_t)row * D_DIM);
    const float4* xr   = (const float4*)(x      + (size_t)row * D_DIM);
    float4*       orow = (float4*)(out + (size_t)row * D_DIM);
    const float4* gr   = (const float4*)g_sgG;

    float4 v[8];
    float sum = 0.0f;
    #pragma unroll
    for (int i = 0; i < 8; i++) {
        v[i] = yr[lane + 32 * i];
        sum += (v[i].x + v[i].y) + (v[i].z + v[i].w);
    }
    #pragma unroll
    for (int o = 16; o > 0; o >>= 1) sum += __shfl_xor_sync(0xffffffffu, sum, o);
    const float mean = sum * (1.0f / 1024.0f);

    float ss = 0.0f;
    #pragma unroll
    for (int i = 0; i < 8; i++) {
        float dx = v[i].x - mean, dy = v[i].y - mean;
        float dz = v[i].z - mean, dw = v[i].w - mean;
        ss += (dx * dx + dy * dy) + (dz * dz + dw * dw);
    }
    #pragma unroll
    for (int o = 16; o > 0; o >>= 1) ss += __shfl_xor_sync(0xffffffffu, ss, o);
    const float rstd = rsqrtf(ss * (1.0f / 1024.0f) + 1e-5f);

    #pragma unroll
    for (int i = 0; i < 8; i++) {
        float4 g4 = gr[lane + 32 * i];
        float4 x4 = xr[lane + 32 * i];
        float4 o4;
        o4.x = fminf(fmaxf((v[i].x - mean) * rstd * g4.x + x4.x, 0.0f), 1.0f);
        o4.y = fminf(fmaxf((v[i].y - mean) * rstd * g4.y + x4.y, 0.0f), 1.0f);
        o4.z = fminf(fmaxf((v[i].z - mean) * rstd * g4.z + x4.z, 0.0f), 1.0f);
        o4.w = fminf(fmaxf((v[i].w - mean) * rstd * g4.w + x4.w, 0.0f), 1.0f);
        orow[lane + 32 * i] = o4;
    }
}

// ---------------------------------------------------------------------------
// Launch order note: two no-op launches pad the sequence so ncu's `-s 5 -c 1`
// captures recur_kernel (launch index 5) instead of ln_kernel.
// ---------------------------------------------------------------------------
extern "C" void kernel_launch(void* const* d_in, const int* in_sizes, int n_in,
                              void* d_out, int out_size) {
    const float* x     = (const float*)d_in[0];
    const float* A     = (const float*)d_in[1];
    const float* WB    = (const float*)d_in[2];
    const float* WC    = (const float*)d_in[3];
    const float* gamma = (const float*)d_in[4];
    float* out = (float*)d_out;

    precompute_kernel<<<256, 256>>>(A, WB, WC, gamma);            // 0
    bproj_gemm<<<M_TOT / 128, 256>>>(x);                          // 1
    aux_kernel<<<(M_TOT + 2 * D_DIM + 255) / 256, 256>>>();       // 2
    noop_kernel<<<1, 32>>>();                                     // 3
    noop_kernel<<<1, 32>>>();                                     // 4
    recur_kernel<<<128, 256>>>(x);                                // 5
    ln_kernel<<<M_TOT / 8, 256>>>(x, out);                        // 6
}

// round 9
// speedup vs baseline: 2.6107x; 1.3126x over previous
#include <cuda_runtime.h>
#include <cuda_bf16.h>

#define S_LEN  1024
#define D_DIM  1024
#define N_ST   64
#define B_SZ   16
#define M_TOT  (B_SZ * S_LEN)

typedef unsigned long long u64;

// ---------------------------------------------------------------------------
// Scratch (device globals; no runtime allocation allowed)
// ---------------------------------------------------------------------------
__device__ float g_sgA[D_DIM * N_ST];
__device__ float g_sgB[N_ST * D_DIM];
__device__ float g_sgC[D_DIM * N_ST];
__device__ float g_sgG[D_DIM];
__device__ float g_bproj[M_TOT * N_ST];
__device__ float g_minb[M_TOT];                 // min_n bproj[row, n]
__device__ float g_sumCh[D_DIM * 2];            // per (d, half) sum of sgC
__device__ float g_yraw[(size_t)M_TOT * D_DIM];

__device__ __forceinline__ float sigf(float v) { return 1.0f / (1.0f + expf(-v)); }

// ---- packed f32x2 helpers (Blackwell sm_103a) ------------------------------
__device__ __forceinline__ u64 pk2(float lo, float hi) {
    u64 r; asm("mov.b64 %0, {%1, %2};" : "=l"(r) : "f"(lo), "f"(hi)); return r;
}
__device__ __forceinline__ void upk2(u64 v, float& lo, float& hi) {
    asm("mov.b64 {%0, %1}, %2;" : "=f"(lo), "=f"(hi) : "l"(v));
}
__device__ __forceinline__ u64 fma2_(u64 a, u64 b, u64 c) {
    u64 d; asm("fma.rn.f32x2 %0, %1, %2, %3;" : "=l"(d) : "l"(a), "l"(b), "l"(c)); return d;
}
__device__ __forceinline__ u64 mul2_(u64 a, u64 b) {
    u64 d; asm("mul.rn.f32x2 %0, %1, %2;" : "=l"(d) : "l"(a), "l"(b)); return d;
}
__device__ __forceinline__ u64 min1_2(u64 v) {
    float lo, hi;
    upk2(v, lo, hi);
    lo = fminf(lo, 1.0f);
    hi = fminf(hi, 1.0f);
    return pk2(lo, hi);
}

// ---------------------------------------------------------------------------
// K1: precompute sigmoids + sumCh (fused)
// ---------------------------------------------------------------------------
__global__ void precompute_kernel(const float* __restrict__ A,
                                  const float* __restrict__ WB,
                                  const float* __restrict__ WC,
                                  const float* __restrict__ gamma) {
    int i = blockIdx.x * blockDim.x + threadIdx.x;
    if (i < D_DIM * N_ST) {
        g_sgA[i] = sigf(A[i]);
        g_sgB[i] = sigf(WB[i]);
        g_sgC[i] = sigf(WC[i]);
    }
    if (i < D_DIM) g_sgG[i] = sigf(gamma[i]);
    if (i < 2 * D_DIM) {                       // sumCh[d*2+half]
        int d = i >> 1, half = i & 1;
        const float* c = WC + (size_t)d * N_ST + half * 32;
        float s = 0.0f;
        #pragma unroll
        for (int q = 0; q < 32; q++) s += sigf(c[q]);
        g_sumCh[i] = s;
    }
}

// ---------------------------------------------------------------------------
// K2: Bproj = x @ sgB.T  (M=16384, K=1024, N=64). Double-buffered smem,
// packed-n accumulators (4 m-rows x 4 n-pairs per thread), fused row-min
// epilogue for g_minb.
// ---------------------------------------------------------------------------
__global__ __launch_bounds__(256) void bproj_gemm(const float* __restrict__ X) {
    __shared__ __align__(16) float xs[2][16][128];   // [stage][k][m]
    __shared__ __align__(16) float bs[2][16][64];    // [stage][k][n]

    const int m0   = blockIdx.x * 128;
    const int tid  = threadIdx.x;
    const int trow = tid >> 3;      // 0..31 -> rows trow*4 .. +3
    const int tcol = tid & 7;       // 0..7  -> cols tcol*8 .. +7 (4 pairs)

    u64 acc[4][4];                  // [m][n-pair]
    #pragma unroll
    for (int i = 0; i < 4; i++)
        #pragma unroll
        for (int j = 0; j < 4; j++) acc[i][j] = 0ull;

    const int xm  = tid & 127, xkq = tid >> 7;   // x tile: 2 float4/thread
    const int bn  = tid & 63,  bkq = tid >> 6;   // b tile: 1 float4/thread

    // prologue: load stage 0
    {
        const float4* xg = (const float4*)(X + (size_t)(m0 + xm) * D_DIM + xkq * 8);
        #pragma unroll
        for (int j = 0; j < 2; j++) {
            float4 v = xg[j];
            const int k = xkq * 8 + j * 4;
            xs[0][k + 0][xm] = v.x; xs[0][k + 1][xm] = v.y;
            xs[0][k + 2][xm] = v.z; xs[0][k + 3][xm] = v.w;
        }
        float4 v = *(const float4*)(g_sgB + (size_t)bn * D_DIM + bkq * 4);
        const int k = bkq * 4;
        bs[0][k + 0][bn] = v.x; bs[0][k + 1][bn] = v.y;
        bs[0][k + 2][bn] = v.z; bs[0][k + 3][bn] = v.w;
    }
    __syncthreads();

    for (int it = 0; it < 64; it++) {
        const int cur = it & 1, nxt = cur ^ 1;
        float4 xr0, xr1, br;
        if (it < 63) {
            const int k0 = (it + 1) * 16;
            const float4* xg = (const float4*)(X + (size_t)(m0 + xm) * D_DIM + k0 + xkq * 8);
            xr0 = xg[0];
            xr1 = xg[1];
            br  = *(const float4*)(g_sgB + (size_t)bn * D_DIM + k0 + bkq * 4);
        }

        #pragma unroll
        for (int kk = 0; kk < 16; kk++) {
            float4 xv = *(const float4*)&xs[cur][kk][trow * 4];          // 4 m-vals
            const ulonglong2* brow = (const ulonglong2*)&bs[cur][kk][0];
            ulonglong2 b01 = brow[tcol * 2 + 0];                         // pairs 0,1
            ulonglong2 b23 = brow[tcol * 2 + 1];                         // pairs 2,3
            u64 xd[4];
            xd[0] = pk2(xv.x, xv.x); xd[1] = pk2(xv.y, xv.y);
            xd[2] = pk2(xv.z, xv.z); xd[3] = pk2(xv.w, xv.w);
            #pragma unroll
            for (int i = 0; i < 4; i++) {
                acc[i][0] = fma2_(b01.x, xd[i], acc[i][0]);
                acc[i][1] = fma2_(b01.y, xd[i], acc[i][1]);
                acc[i][2] = fma2_(b23.x, xd[i], acc[i][2]);
                acc[i][3] = fma2_(b23.y, xd[i], acc[i][3]);
            }
        }

        if (it < 63) {
            const int k = xkq * 8;
            xs[nxt][k + 0][xm] = xr0.x; xs[nxt][k + 1][xm] = xr0.y;
            xs[nxt][k + 2][xm] = xr0.z; xs[nxt][k + 3][xm] = xr0.w;
            xs[nxt][k + 4][xm] = xr1.x; xs[nxt][k + 5][xm] = xr1.y;
            xs[nxt][k + 6][xm] = xr1.z; xs[nxt][k + 7][xm] = xr1.w;
            const int kb = bkq * 4;
            bs[nxt][kb + 0][bn] = br.x; bs[nxt][kb + 1][bn] = br.y;
            bs[nxt][kb + 2][bn] = br.z; bs[nxt][kb + 3][bn] = br.w;
        }
        __syncthreads();
    }

    // writeback + fused row-min (cols tcol*8+2j, +2j+1 are pair j of acc row)
    #pragma unroll
    for (int i = 0; i < 4; i++) {
        const int row = m0 + trow * 4 + i;
        ulonglong2* p = (ulonglong2*)(g_bproj + (size_t)row * N_ST + tcol * 8);
        p[0] = make_ulonglong2(acc[i][0], acc[i][1]);
        p[1] = make_ulonglong2(acc[i][2], acc[i][3]);

        float mn = 1e30f;
        #pragma unroll
        for (int j = 0; j < 4; j++) {
            float lo, hi;
            upk2(acc[i][j], lo, hi);
            mn = fminf(mn, fminf(lo, hi));
        }
        mn = fminf(mn, __shfl_xor_sync(0xffffffffu, mn, 1));
        mn = fminf(mn, __shfl_xor_sync(0xffffffffu, mn, 2));
        mn = fminf(mn, __shfl_xor_sync(0xffffffffu, mn, 4));
        if (tcol == 0) g_minb[row] = mn;
    }
}

__global__ void noop_kernel() {}

// ---------------------------------------------------------------------------
// K3: recurrence with exact saturation fast path. 8-step groups, 16-row smem
// ring, hone-reset hoisted out of the slow loop.
// ---------------------------------------------------------------------------
__global__ __launch_bounds__(256, 1) void recur_kernel(const float* __restrict__ x) {
    const int b    = blockIdx.x >> 3;
    const int tid  = threadIdx.x;
    const int dl   = tid >> 1;
    const int half = tid & 1;
    const int d    = ((blockIdx.x & 7) << 7) | dl;

    u64 a[16], c[16], h[16];
    {
        const ulonglong2* ar = (const ulonglong2*)(g_sgA + (size_t)d * N_ST + half * 32);
        const ulonglong2* cr = (const ulonglong2*)(g_sgC + (size_t)d * N_ST + half * 32);
        #pragma unroll
        for (int q = 0; q < 8; q++) {
            ulonglong2 av = ar[q], cv = cr[q];
            a[2 * q] = av.x; a[2 * q + 1] = av.y;
            c[2 * q] = cv.x; c[2 * q + 1] = cv.y;
            h[2 * q] = 0ull; h[2 * q + 1] = 0ull;
        }
    }
    const float sumCh = g_sumCh[((blockIdx.x & 7) << 8) | tid];   // = d*2+half
    const u64 one2 = pk2(1.0f, 1.0f);
    bool hone = false;

    __shared__ ulonglong2 bb[16][16];      // 16-row ring, interleaved chunks
    const ulonglong2* bp = (const ulonglong2*)(g_bproj + (size_t)b * S_LEN * N_ST);
    const float* xp = x      + (size_t)b * S_LEN * D_DIM + d;
    const float* mp = g_minb + (size_t)b * S_LEN;
    float*       yp = g_yraw + (size_t)b * S_LEN * D_DIM + d;

    // preload rows 0..7 (128 threads x 16B) and x/minb[0..7]
    if (tid < 128) {
        const int r = tid >> 4, cch = tid & 15;
        bb[r][((cch & 7) << 1) | (cch >> 3)] = bp[(size_t)r * 16 + cch];
    }
    float xc[8], mc[8];
    #pragma unroll
    for (int i = 0; i < 8; i++) {
        xc[i] = xp[(size_t)i * D_DIM];
        mc[i] = mp[i];
    }
    __syncthreads();

    for (int g = 0; g < S_LEN / 8; g++) {
        const int t0i = g * 8;
        float xn[8], mn_[8];
        #pragma unroll
        for (int i = 0; i < 8; i++) { xn[i] = 0.f; mn_[i] = 0.f; }
        if (g < S_LEN / 8 - 1) {
            if (tid < 128) {
                const int r = t0i + 8 + (tid >> 4), cch = tid & 15;
                bb[r & 15][((cch & 7) << 1) | (cch >> 3)] = bp[(size_t)r * 16 + cch];
            }
            #pragma unroll
            for (int i = 0; i < 8; i++) {
                xn[i]  = xp[(size_t)(t0i + 8 + i) * D_DIM];
                mn_[i] = mp[t0i + 8 + i];
            }
        }

        #pragma unroll
        for (int tt = 0; tt < 8; tt++) {
            const float xv = xc[tt];
            float part;
            if (xv * mc[tt] >= 1.0f) {
                part = sumCh;              // exact: h saturates to 1 for all n
                hone = true;
            } else {
                if (hone) {
                    #pragma unroll
                    for (int q = 0; q < 16; q++) h[q] = one2;
                    hone = false;
                }
                const ulonglong2* bcur = bb[(t0i + tt) & 15];
                const u64 xx = pk2(xv, xv);
                u64 y0 = 0ull, y1 = 0ull;
                #pragma unroll
                for (int q = 0; q < 8; q++) {
                    ulonglong2 bv = bcur[2 * q + half];
                    u64 p0 = min1_2(fma2_(bv.x, xx, mul2_(h[2 * q],     a[2 * q])));
                    u64 p1 = min1_2(fma2_(bv.y, xx, mul2_(h[2 * q + 1], a[2 * q + 1])));
                    h[2 * q]     = p0;
                    h[2 * q + 1] = p1;
                    y0 = fma2_(p0, c[2 * q],     y0);
                    y1 = fma2_(p1, c[2 * q + 1], y1);
                }
                float s0, s1, s2, s3;
                upk2(y0, s0, s1);
                upk2(y1, s2, s3);
                part = (s0 + s1) + (s2 + s3);
            }
            float tot = part + __shfl_xor_sync(0xffffffffu, part, 1);
            if (half == 0) yp[(size_t)(t0i + tt) * D_DIM] = tot;
        }

        #pragma unroll
        for (int i = 0; i < 8; i++) { xc[i] = xn[i]; mc[i] = mn_[i]; }
        __syncthreads();
    }
}

// ---------------------------------------------------------------------------
// K4: deferred TopologicalNorm + residual + clip (two-pass, row in regs)
// ---------------------------------------------------------------------------
__global__ __launch_bounds__(256) void ln_kernel(const float* __restrict__ x,
                                                 float* __restrict__ out) {
    const int row  = blockIdx.x * 8 + (threadIdx.x >> 5);
    const int lane = threadIdx.x & 31;

    const float4* yr   = (const float4*)(g_yraw + (size_t)row * D_DIM);
    const float4* xr   = (const float4*)(x      + (size_t)row * D_DIM);
    float4*       orow = (float4*)(out + (size_t)row * D_DIM);
    const float4* gr   = (const float4*)g_sgG;

    float4 v[8];
    float sum = 0.0f;
    #pragma unroll
    for (int i = 0; i < 8; i++) {
        v[i] = yr[lane + 32 * i];
        sum += (v[i].x + v[i].y) + (v[i].z + v[i].w);
    }
    #pragma unroll
    for (int o = 16; o > 0; o >>= 1) sum += __shfl_xor_sync(0xffffffffu, sum, o);
    const float mean = sum * (1.0f / 1024.0f);

    float ss = 0.0f;
    #pragma unroll
    for (int i = 0; i < 8; i++) {
        float dx = v[i].x - mean, dy = v[i].y - mean;
        float dz = v[i].z - mean, dw = v[i].w - mean;
        ss += (dx * dx + dy * dy) + (dz * dz + dw * dw);
    }
    #pragma unroll
    for (int o = 16; o > 0; o >>= 1) ss += __shfl_xor_sync(0xffffffffu, ss, o);
    const float rstd = rsqrtf(ss * (1.0f / 1024.0f) + 1e-5f);

    #pragma unroll
    for (int i = 0; i < 8; i++) {
        float4 g4 = gr[lane + 32 * i];
        float4 x4 = xr[lane + 32 * i];
        float4 o4;
        o4.x = fminf(fmaxf((v[i].x - mean) * rstd * g4.x + x4.x, 0.0f), 1.0f);
        o4.y = fminf(fmaxf((v[i].y - mean) * rstd * g4.y + x4.y, 0.0f), 1.0f);
        o4.z = fminf(fmaxf((v[i].z - mean) * rstd * g4.z + x4.z, 0.0f), 1.0f);
        o4.w = fminf(fmaxf((v[i].w - mean) * rstd * g4.w + x4.w, 0.0f), 1.0f);
        orow[lane + 32 * i] = o4;
    }
}

// ---------------------------------------------------------------------------
// ncu captures launch index 3 (0-based) -> recur_kernel this round.
// ---------------------------------------------------------------------------
extern "C" void kernel_launch(void* const* d_in, const int* in_sizes, int n_in,
                              void* d_out, int out_size) {
    const float* x     = (const float*)d_in[0];
    const float* A     = (const float*)d_in[1];
    const float* WB    = (const float*)d_in[2];
    const float* WC    = (const float*)d_in[3];
    const float* gamma = (const float*)d_in[4];
    float* out = (float*)d_out;

    precompute_kernel<<<256, 256>>>(A, WB, WC, gamma);   // 0
    bproj_gemm<<<M_TOT / 128, 256>>>(x);                 // 1
    noop_kernel<<<1, 32>>>();                            // 2
    recur_kernel<<<128, 256>>>(x);                       // 3  <- profiled
    ln_kernel<<<M_TOT / 8, 256>>>(x, out);               // 4
}

// round 10
// speedup vs baseline: 3.3223x; 1.2726x over previous
#include <cuda_runtime.h>
#include <cuda_bf16.h>

#define S_LEN  1024
#define D_DIM  1024
#define N_ST   64
#define B_SZ   16
#define M_TOT  (B_SZ * S_LEN)

typedef unsigned long long u64;

// ---------------------------------------------------------------------------
// Scratch (device globals; no runtime allocation allowed)
// ---------------------------------------------------------------------------
__device__ float g_sgA[D_DIM * N_ST];
__device__ float g_sgB[N_ST * D_DIM];
__device__ float g_sgC[D_DIM * N_ST];
__device__ float g_sgG[D_DIM];
__device__ float g_sumC[D_DIM];                    // full 64-sum of sgC per d
__device__ float g_bproj[M_TOT * N_ST];
__device__ float g_minb[M_TOT];                    // min_n bproj[row, n]
__device__ unsigned g_mask[M_TOT * D_DIM / 32];    // non-sat bitmask (2 MB)
__device__ float g_yraw[(size_t)M_TOT * D_DIM];    // sparse corrections only

__device__ __forceinline__ float sigf(float v) { return 1.0f / (1.0f + expf(-v)); }

// ---- packed f32x2 helpers (Blackwell sm_103a) ------------------------------
__device__ __forceinline__ u64 pk2(float lo, float hi) {
    u64 r; asm("mov.b64 %0, {%1, %2};" : "=l"(r) : "f"(lo), "f"(hi)); return r;
}
__device__ __forceinline__ void upk2(u64 v, float& lo, float& hi) {
    asm("mov.b64 {%0, %1}, %2;" : "=f"(lo), "=f"(hi) : "l"(v));
}
__device__ __forceinline__ u64 fma2_(u64 a, u64 b, u64 c) {
    u64 d; asm("fma.rn.f32x2 %0, %1, %2, %3;" : "=l"(d) : "l"(a), "l"(b), "l"(c)); return d;
}

// ---------------------------------------------------------------------------
// K1: precompute sigmoids + sumC
// ---------------------------------------------------------------------------
__global__ void precompute_kernel(const float* __restrict__ A,
                                  const float* __restrict__ WB,
                                  const float* __restrict__ WC,
                                  const float* __restrict__ gamma) {
    int i = blockIdx.x * blockDim.x + threadIdx.x;
    if (i < D_DIM * N_ST) {
        g_sgA[i] = sigf(A[i]);
        g_sgB[i] = sigf(WB[i]);
        g_sgC[i] = sigf(WC[i]);
    }
    if (i < D_DIM) {
        g_sgG[i] = sigf(gamma[i]);
        const float* c = WC + (size_t)i * N_ST;
        float s = 0.0f;
        #pragma unroll
        for (int q = 0; q < N_ST; q++) s += sigf(c[q]);
        g_sumC[i] = s;
    }
}

// ---------------------------------------------------------------------------
// K2: Bproj = x @ sgB.T (M=16384, K=1024, N=64). Double-buffered smem,
// packed-n accumulators, fused row-min epilogue. (Profiled this round.)
// ---------------------------------------------------------------------------
__global__ __launch_bounds__(256) void bproj_gemm(const float* __restrict__ X) {
    __shared__ __align__(16) float xs[2][16][128];
    __shared__ __align__(16) float bs[2][16][64];

    const int m0   = blockIdx.x * 128;
    const int tid  = threadIdx.x;
    const int trow = tid >> 3;
    const int tcol = tid & 7;

    u64 acc[4][4];
    #pragma unroll
    for (int i = 0; i < 4; i++)
        #pragma unroll
        for (int j = 0; j < 4; j++) acc[i][j] = 0ull;

    const int xm  = tid & 127, xkq = tid >> 7;
    const int bn  = tid & 63,  bkq = tid >> 6;

    {
        const float4* xg = (const float4*)(X + (size_t)(m0 + xm) * D_DIM + xkq * 8);
        #pragma unroll
        for (int j = 0; j < 2; j++) {
            float4 v = xg[j];
            const int k = xkq * 8 + j * 4;
            xs[0][k + 0][xm] = v.x; xs[0][k + 1][xm] = v.y;
            xs[0][k + 2][xm] = v.z; xs[0][k + 3][xm] = v.w;
        }
        float4 v = *(const float4*)(g_sgB + (size_t)bn * D_DIM + bkq * 4);
        const int k = bkq * 4;
        bs[0][k + 0][bn] = v.x; bs[0][k + 1][bn] = v.y;
        bs[0][k + 2][bn] = v.z; bs[0][k + 3][bn] = v.w;
    }
    __syncthreads();

    for (int it = 0; it < 64; it++) {
        const int cur = it & 1, nxt = cur ^ 1;
        float4 xr0, xr1, br;
        if (it < 63) {
            const int k0 = (it + 1) * 16;
            const float4* xg = (const float4*)(X + (size_t)(m0 + xm) * D_DIM + k0 + xkq * 8);
            xr0 = xg[0];
            xr1 = xg[1];
            br  = *(const float4*)(g_sgB + (size_t)bn * D_DIM + k0 + bkq * 4);
        }

        #pragma unroll
        for (int kk = 0; kk < 16; kk++) {
            float4 xv = *(const float4*)&xs[cur][kk][trow * 4];
            const ulonglong2* brow = (const ulonglong2*)&bs[cur][kk][0];
            ulonglong2 b01 = brow[tcol * 2 + 0];
            ulonglong2 b23 = brow[tcol * 2 + 1];
            u64 xd[4];
            xd[0] = pk2(xv.x, xv.x); xd[1] = pk2(xv.y, xv.y);
            xd[2] = pk2(xv.z, xv.z); xd[3] = pk2(xv.w, xv.w);
            #pragma unroll
            for (int i = 0; i < 4; i++) {
                acc[i][0] = fma2_(b01.x, xd[i], acc[i][0]);
                acc[i][1] = fma2_(b01.y, xd[i], acc[i][1]);
                acc[i][2] = fma2_(b23.x, xd[i], acc[i][2]);
                acc[i][3] = fma2_(b23.y, xd[i], acc[i][3]);
            }
        }

        if (it < 63) {
            const int k = xkq * 8;
            xs[nxt][k + 0][xm] = xr0.x; xs[nxt][k + 1][xm] = xr0.y;
            xs[nxt][k + 2][xm] = xr0.z; xs[nxt][k + 3][xm] = xr0.w;
            xs[nxt][k + 4][xm] = xr1.x; xs[nxt][k + 5][xm] = xr1.y;
            xs[nxt][k + 6][xm] = xr1.z; xs[nxt][k + 7][xm] = xr1.w;
            const int kb = bkq * 4;
            bs[nxt][kb + 0][bn] = br.x; bs[nxt][kb + 1][bn] = br.y;
            bs[nxt][kb + 2][bn] = br.z; bs[nxt][kb + 3][bn] = br.w;
        }
        __syncthreads();
    }

    #pragma unroll
    for (int i = 0; i < 4; i++) {
        const int row = m0 + trow * 4 + i;
        ulonglong2* p = (ulonglong2*)(g_bproj + (size_t)row * N_ST + tcol * 8);
        p[0] = make_ulonglong2(acc[i][0], acc[i][1]);
        p[1] = make_ulonglong2(acc[i][2], acc[i][3]);

        float mn = 1e30f;
        #pragma unroll
        for (int j = 0; j < 4; j++) {
            float lo, hi;
            upk2(acc[i][j], lo, hi);
            mn = fminf(mn, fminf(lo, hi));
        }
        mn = fminf(mn, __shfl_xor_sync(0xffffffffu, mn, 1));
        mn = fminf(mn, __shfl_xor_sync(0xffffffffu, mn, 2));
        mn = fminf(mn, __shfl_xor_sync(0xffffffffu, mn, 4));
        if (tcol == 0) g_minb[row] = mn;
    }
}

__global__ void noop_kernel() {}

// ---------------------------------------------------------------------------
// K3a: scan — build non-sat bitmask. One thread = 32 consecutive elements
// (one mask word, all in one (b,t) row). No atomics, lean registers.
// ---------------------------------------------------------------------------
__global__ __launch_bounds__(256) void scan_kernel(const float* __restrict__ x) {
    const int w   = blockIdx.x * 256 + threadIdx.x;      // word index
    const int row = w >> 5;                               // (b*S + t)
    const float mb = g_minb[row];
    const float4* xp = (const float4*)(x + ((size_t)w << 5));

    unsigned m = 0u;
    #pragma unroll
    for (int j = 0; j < 8; j++) {
        float4 v = xp[j];
        if (v.x * mb < 1.0f) m |= 1u << (4 * j + 0);
        if (v.y * mb < 1.0f) m |= 1u << (4 * j + 1);
        if (v.z * mb < 1.0f) m |= 1u << (4 * j + 2);
        if (v.w * mb < 1.0f) m |= 1u << (4 * j + 3);
    }
    g_mask[w] = m;
}

// ---------------------------------------------------------------------------
// K3b: fixer — for each non-sat element, walk back to the last saturating
// step (h there = exactly 1 for all n), recur forward, scatter y correction.
// Expected ~65K of 16M elements; chains expected length ~1.
// ---------------------------------------------------------------------------
__device__ void fix_one(const float* __restrict__ x, int row0, int t, int d) {
    int s = t - 1;
    while (s >= 0) {
        float xs = x[((size_t)(row0 + s) << 10) + d];
        if (xs * g_minb[row0 + s] >= 1.0f) break;
        s--;
    }
    float h[N_ST];
    const float hinit = (s >= 0) ? 1.0f : 0.0f;
    #pragma unroll
    for (int n = 0; n < N_ST; n++) h[n] = hinit;

    const float4* ar = (const float4*)(g_sgA + (size_t)d * N_ST);
    for (int u = s + 1; u <= t; u++) {
        const float xu = x[((size_t)(row0 + u) << 10) + d];
        const float4* bp = (const float4*)(g_bproj + ((size_t)(row0 + u) << 6));
        #pragma unroll
        for (int q = 0; q < 16; q++) {
            float4 av = ar[q];
            float4 bv = bp[q];
            h[4 * q + 0] = fminf(fmaf(bv.x, xu, h[4 * q + 0] * av.x), 1.0f);
            h[4 * q + 1] = fminf(fmaf(bv.y, xu, h[4 * q + 1] * av.y), 1.0f);
            h[4 * q + 2] = fminf(fmaf(bv.z, xu, h[4 * q + 2] * av.z), 1.0f);
            h[4 * q + 3] = fminf(fmaf(bv.w, xu, h[4 * q + 3] * av.w), 1.0f);
        }
    }

    const float4* cr = (const float4*)(g_sgC + (size_t)d * N_ST);
    float y0 = 0.f, y1 = 0.f, y2 = 0.f, y3 = 0.f;
    #pragma unroll
    for (int q = 0; q < 16; q++) {
        float4 cv = cr[q];
        y0 = fmaf(h[4 * q + 0], cv.x, y0);
        y1 = fmaf(h[4 * q + 1], cv.y, y1);
        y2 = fmaf(h[4 * q + 2], cv.z, y2);
        y3 = fmaf(h[4 * q + 3], cv.w, y3);
    }
    g_yraw[((size_t)(row0 + t) << 10) + d] = (y0 + y1) + (y2 + y3);
}

__global__ __launch_bounds__(256) void fix_kernel(const float* __restrict__ x) {
    const int NW = M_TOT * D_DIM / 32;
    for (int w = blockIdx.x * 256 + threadIdx.x; w < NW; w += gridDim.x * 256) {
        unsigned m = g_mask[w];
        if (m == 0u) continue;
        const int row  = w >> 5;             // b*S + t
        const int row0 = row & ~(S_LEN - 1); // b*S
        const int t    = row & (S_LEN - 1);
        const int dbase = (w & 31) * 32;
        while (m) {
            const int c = __ffs(m) - 1;
            m &= m - 1;
            fix_one(x, row0, t, dbase + c);
        }
    }
}

// ---------------------------------------------------------------------------
// K4: TopologicalNorm + residual + clip. y is reconstructed per element:
// sat (x*minb>=1, identical fp test as scan/fixer) -> sumC[d]; else the
// fixer's scattered correction in g_yraw.
// ---------------------------------------------------------------------------
__global__ __launch_bounds__(256) void ln_kernel(const float* __restrict__ x,
                                                 float* __restrict__ out) {
    const int row  = blockIdx.x * 8 + (threadIdx.x >> 5);
    const int lane = threadIdx.x & 31;

    const float mb = g_minb[row];
    const float* yrawr = g_yraw + ((size_t)row << 10);
    const float4* xr   = (const float4*)(x + ((size_t)row << 10));
    float4*       orow = (float4*)(out + ((size_t)row << 10));
    const float4* gr   = (const float4*)g_sgG;
    const float4* sr   = (const float4*)g_sumC;

    float4 v[8], xv[8];
    float sum = 0.0f;
    #pragma unroll
    for (int i = 0; i < 8; i++) {
        const int idx = lane + 32 * i;
        float4 x4 = xr[idx];
        float4 s4 = sr[idx];
        float4 y4;
        y4.x = (x4.x * mb >= 1.0f) ? s4.x : yrawr[4 * idx + 0];
        y4.y = (x4.y * mb >= 1.0f) ? s4.y : yrawr[4 * idx + 1];
        y4.z = (x4.z * mb >= 1.0f) ? s4.z : yrawr[4 * idx + 2];
        y4.w = (x4.w * mb >= 1.0f) ? s4.w : yrawr[4 * idx + 3];
        v[i] = y4;
        xv[i] = x4;
        sum += (y4.x + y4.y) + (y4.z + y4.w);
    }
    #pragma unroll
    for (int o = 16; o > 0; o >>= 1) sum += __shfl_xor_sync(0xffffffffu, sum, o);
    const float mean = sum * (1.0f / 1024.0f);

    float ss = 0.0f;
    #pragma unroll
    for (int i = 0; i < 8; i++) {
        float dx = v[i].x - mean, dy = v[i].y - mean;
        float dz = v[i].z - mean, dw = v[i].w - mean;
        ss += (dx * dx + dy * dy) + (dz * dz + dw * dw);
    }
    #pragma unroll
    for (int o = 16; o > 0; o >>= 1) ss += __shfl_xor_sync(0xffffffffu, ss, o);
    const float rstd = rsqrtf(ss * (1.0f / 1024.0f) + 1e-5f);

    #pragma unroll
    for (int i = 0; i < 8; i++) {
        float4 g4 = gr[lane + 32 * i];
        float4 o4;
        o4.x = fminf(fmaxf((v[i].x - mean) * rstd * g4.x + xv[i].x, 0.0f), 1.0f);
        o4.y = fminf(fmaxf((v[i].y - mean) * rstd * g4.y + xv[i].y, 0.0f), 1.0f);
        o4.z = fminf(fmaxf((v[i].z - mean) * rstd * g4.z + xv[i].z, 0.0f), 1.0f);
        o4.w = fminf(fmaxf((v[i].w - mean) * rstd * g4.w + xv[i].w, 0.0f), 1.0f);
        orow[lane + 32 * i] = o4;
    }
}

// ---------------------------------------------------------------------------
// ncu captures 0-based launch index 3 -> bproj_gemm this round.
// ---------------------------------------------------------------------------
extern "C" void kernel_launch(void* const* d_in, const int* in_sizes, int n_in,
                              void* d_out, int out_size) {
    const float* x     = (const float*)d_in[0];
    const float* A     = (const float*)d_in[1];
    const float* WB    = (const float*)d_in[2];
    const float* WC    = (const float*)d_in[3];
    const float* gamma = (const float*)d_in[4];
    float* out = (float*)d_out;

    noop_kernel<<<1, 32>>>();                              // 0
    noop_kernel<<<1, 32>>>();                              // 1
    precompute_kernel<<<256, 256>>>(A, WB, WC, gamma);     // 2
    bproj_gemm<<<M_TOT / 128, 256>>>(x);                   // 3  <- profiled
    scan_kernel<<<M_TOT * D_DIM / 32 / 256, 256>>>(x);     // 4
    fix_kernel<<<1024, 256>>>(x);                          // 5
    ln_kernel<<<M_TOT / 8, 256>>>(x, out);                 // 6
}